// round 8
// baseline (speedup 1.0000x reference)
#include <cuda_runtime.h>
#include <cuda_bf16.h>
#include <cstdint>
#include <cstddef>

#define BATCH   4096
#define TSTEPS  256
#define FDIM    64
#define G4      64      // 4*H
#define HID     16
#define DDIM    64
#define TILE_M  128
#define NROWS_TOT (BATCH * TSTEPS)        // 1048576
#define NTILES    (NROWS_TOT / TILE_M)    // 8192

// scratch: permuted gate pre-activations xw[row][h*4 + gate], fp32
__device__ float g_xw[(size_t)NROWS_TOT * G4];

// ---------------- helpers ----------------
__device__ __forceinline__ uint32_t pack_bf16_hi(float a, float b) {
    __nv_bfloat16 ha = __float2bfloat16_rn(a);
    __nv_bfloat16 hb = __float2bfloat16_rn(b);
    return ((uint32_t)__bfloat16_as_ushort(hb) << 16) | (uint32_t)__bfloat16_as_ushort(ha);
}
__device__ __forceinline__ uint32_t pack_bf16_lo(float a, float b) {
    __nv_bfloat16 ha = __float2bfloat16_rn(a);
    __nv_bfloat16 hb = __float2bfloat16_rn(b);
    __nv_bfloat16 la = __float2bfloat16_rn(a - __bfloat162float(ha));
    __nv_bfloat16 lb = __float2bfloat16_rn(b - __bfloat162float(hb));
    return ((uint32_t)__bfloat16_as_ushort(lb) << 16) | (uint32_t)__bfloat16_as_ushort(la);
}

// warp-level bf16 MMA, sm_80+ (works on base sm_103 target)
__device__ __forceinline__ void mma16816(float* c, const uint32_t* a,
                                         uint32_t b0, uint32_t b1) {
    asm volatile(
        "mma.sync.aligned.m16n8k16.row.col.f32.bf16.bf16.f32 "
        "{%0,%1,%2,%3}, {%4,%5,%6,%7}, {%8,%9}, {%0,%1,%2,%3};"
        : "+f"(c[0]), "+f"(c[1]), "+f"(c[2]), "+f"(c[3])
        : "r"(a[0]), "r"(a[1]), "r"(a[2]), "r"(a[3]), "r"(b0), "r"(b1));
}

// ================= Kernel 1: xw = x @ W  (bf16 hi/lo split, mma.sync) =================
// CTA = 128 threads = 4 warps; warp w computes rows [32w, 32w+32) of a 128-row tile.
// B columns pre-permuted so output col j == gate-permuted index h*4+gate directly.
// A fragments loaded straight from gmem (LDG.64, fully sector-coalesced).
__global__ void __launch_bounds__(128, 4)
gemm_xw_kernel(const float* __restrict__ xg, const float* __restrict__ Wg)
{
    // Bs[kp*68 + j] = (hi, lo) bf16x2 pair of { Bp[2kp][j], Bp[2kp+1][j] },
    // Bp[k][j] = W[k][(j%4)*16 + j/4].  stride 68 -> <=2-way LDS conflicts.
    __shared__ uint2 Bs[32 * 68];

    const int tid  = threadIdx.x;
    const int lane = tid & 31;
    const int w    = tid >> 5;
    const int g    = lane >> 2;   // groupID 0..7
    const int kq   = lane & 3;    // threadID_in_group 0..3

    // ---- build permuted B in smem ----
    for (int idx = tid; idx < 2048; idx += 128) {
        int kp = idx >> 6;            // 0..31 (k = 2*kp)
        int j  = idx & 63;            // permuted output column
        int c  = (j & 3) * 16 + (j >> 2);   // original W column
        float w0 = Wg[(2 * kp)     * G4 + c];
        float w1 = Wg[(2 * kp + 1) * G4 + c];
        Bs[kp * 68 + j] = make_uint2(pack_bf16_hi(w0, w1), pack_bf16_lo(w0, w1));
    }
    __syncthreads();

    float acc[2][8][4];
    #pragma unroll
    for (int mt = 0; mt < 2; mt++)
        #pragma unroll
        for (int n = 0; n < 8; n++)
            #pragma unroll
            for (int r = 0; r < 4; r++) acc[mt][n][r] = 0.0f;

    const size_t rowbase = (size_t)blockIdx.x * TILE_M + (size_t)w * 32;

    #pragma unroll
    for (int kk = 0; kk < 4; kk++) {
        // ---- A fragments for both 16-row m-tiles (direct from gmem) ----
        uint32_t ah[2][4], al[2][4];
        #pragma unroll
        for (int mt = 0; mt < 2; mt++) {
            const float* base = xg + (rowbase + (size_t)(mt * 16 + g)) * FDIM
                                   + 2 * kq + 16 * kk;
            float2 v00 = *(const float2*)(base);                 // row g,   k0..k0+1
            float2 v02 = *(const float2*)(base + 8);             // row g,   k0+8..9
            float2 v10 = *(const float2*)(base + 8 * FDIM);      // row g+8, k0..k0+1
            float2 v12 = *(const float2*)(base + 8 * FDIM + 8);  // row g+8, k0+8..9
            ah[mt][0] = pack_bf16_hi(v00.x, v00.y);
            ah[mt][1] = pack_bf16_hi(v10.x, v10.y);
            ah[mt][2] = pack_bf16_hi(v02.x, v02.y);
            ah[mt][3] = pack_bf16_hi(v12.x, v12.y);
            al[mt][0] = pack_bf16_lo(v00.x, v00.y);
            al[mt][1] = pack_bf16_lo(v10.x, v10.y);
            al[mt][2] = pack_bf16_lo(v02.x, v02.y);
            al[mt][3] = pack_bf16_lo(v12.x, v12.y);
        }
        // ---- B fragments per n-tile; 3 products per (mt, n) ----
        #pragma unroll
        for (int n = 0; n < 8; n++) {
            int j = 8 * n + g;
            uint2 b0 = Bs[(kq + 8 * kk)     * 68 + j];   // k-pair k0,   (hi,lo)
            uint2 b1 = Bs[(kq + 4 + 8 * kk) * 68 + j];   // k-pair k0+8, (hi,lo)
            #pragma unroll
            for (int mt = 0; mt < 2; mt++) {
                mma16816(acc[mt][n], ah[mt], b0.x, b1.x);   // hi*hi
                mma16816(acc[mt][n], al[mt], b0.x, b1.x);   // lo*hi
                mma16816(acc[mt][n], ah[mt], b0.y, b1.y);   // hi*lo
            }
        }
    }

    // ---- epilogue: columns are already gate-permuted; contiguous float2 stores ----
    #pragma unroll
    for (int mt = 0; mt < 2; mt++) {
        size_t r0 = rowbase + (size_t)(mt * 16 + g);
        #pragma unroll
        for (int n = 0; n < 8; n++) {
            int j0 = 8 * n + 2 * kq;
            *(float2*)(g_xw + r0 * G4 + j0)       = make_float2(acc[mt][n][0], acc[mt][n][1]);
            *(float2*)(g_xw + (r0 + 8) * G4 + j0) = make_float2(acc[mt][n][2], acc[mt][n][3]);
        }
    }
}

// ================= Kernel 2: recurrence + dense + normalize =================
// 16 threads per batch row. Thread k owns h[k], c[k] and gate columns k, k+16, k+32, k+48.
// U kept entirely in registers; h exchanged via width-16 shuffles.
__global__ void __launch_bounds__(128)
lstm_rec_kernel(const float* __restrict__ Ug, const float* __restrict__ bg,
                const float* __restrict__ Wdg, const float* __restrict__ bdg,
                float* __restrict__ outg)
{
    const int k   = threadIdx.x & 15;
    const int row = blockIdx.x * 8 + (threadIdx.x >> 4);

    float u0[HID], u1[HID], u2[HID], u3[HID];
    #pragma unroll
    for (int j = 0; j < HID; j++) {
        const float* uj = Ug + j * G4;
        u0[j] = uj[k];
        u1[j] = uj[k + 16];
        u2[j] = uj[k + 32];
        u3[j] = uj[k + 48];
    }
    const float b0 = bg[k], b1 = bg[k + 16], b2 = bg[k + 32], b3 = bg[k + 48];

    float h = 0.0f, c = 0.0f;
    const float4* xp = (const float4*)(g_xw + (size_t)row * TSTEPS * G4) + k;
    float4 cur = xp[0];

    for (int t = 0; t < TSTEPS; t++) {
        float4 nxt = cur;
        if (t + 1 < TSTEPS) nxt = xp[(t + 1) * 16];   // prefetch next step

        float hj[HID];
        #pragma unroll
        for (int j = 0; j < HID; j++) hj[j] = __shfl_sync(0xffffffffu, h, j, 16);

        float z0 = cur.x + b0, z1 = cur.y + b1, z2 = cur.z + b2, z3 = cur.w + b3;
        #pragma unroll
        for (int j = 0; j < HID; j++) {
            z0 = fmaf(hj[j], u0[j], z0);
            z1 = fmaf(hj[j], u1[j], z1);
            z2 = fmaf(hj[j], u2[j], z2);
            z3 = fmaf(hj[j], u3[j], z3);
        }
        float ig = __fdividef(1.0f, 1.0f + __expf(-z0));
        float fg = __fdividef(1.0f, 1.0f + __expf(-z1));
        float gg = fmaxf(z2, 0.0f);
        float og = __fdividef(1.0f, 1.0f + __expf(-z3));
        c = fmaf(fg, c, ig * gg);
        h = og * fmaxf(c, 0.0f);
        cur = nxt;
    }

    // dense: out = sigmoid(h @ Wd + bd), thread k computes cols 4k..4k+3
    float hj[HID];
    #pragma unroll
    for (int j = 0; j < HID; j++) hj[j] = __shfl_sync(0xffffffffu, h, j, 16);

    float a0 = 0.f, a1 = 0.f, a2 = 0.f, a3 = 0.f;
    #pragma unroll
    for (int j = 0; j < HID; j++) {
        float4 w4 = *(const float4*)(Wdg + j * DDIM + 4 * k);
        a0 = fmaf(hj[j], w4.x, a0);
        a1 = fmaf(hj[j], w4.y, a1);
        a2 = fmaf(hj[j], w4.z, a2);
        a3 = fmaf(hj[j], w4.w, a3);
    }
    float4 bd4 = *(const float4*)(bdg + 4 * k);
    a0 = __fdividef(1.0f, 1.0f + __expf(-(a0 + bd4.x)));
    a1 = __fdividef(1.0f, 1.0f + __expf(-(a1 + bd4.y)));
    a2 = __fdividef(1.0f, 1.0f + __expf(-(a2 + bd4.z)));
    a3 = __fdividef(1.0f, 1.0f + __expf(-(a3 + bd4.w)));

    float s = a0 + a1 + a2 + a3;
    #pragma unroll
    for (int off = 8; off; off >>= 1) s += __shfl_xor_sync(0xffffffffu, s, off, 16);
    float inv = __fdividef(1.0f, s);

    float4 o4 = make_float4(a0 * inv, a1 * inv, a2 * inv, a3 * inv);
    *((float4*)(outg + (size_t)row * DDIM + 4 * k)) = o4;
}

// ================= launch =================
extern "C" void kernel_launch(void* const* d_in, const int* in_sizes, int n_in,
                              void* d_out, int out_size)
{
    const float* x  = (const float*)d_in[0];
    const float* W  = (const float*)d_in[1];
    const float* U  = (const float*)d_in[2];
    const float* b  = (const float*)d_in[3];
    const float* Wd = (const float*)d_in[4];
    const float* bd = (const float*)d_in[5];
    float* out = (float*)d_out;

    gemm_xw_kernel<<<NTILES, 128>>>(x, W);
    lstm_rec_kernel<<<BATCH / 8, 128>>>(U, b, Wd, bd, out);
}